// round 9
// baseline (speedup 1.0000x reference)
#include <cuda_runtime.h>
#include <math.h>

// ============================================================================
// CKConv via FFT convolution, fused tf32 tensor-core spectrum GEMM.
//   Outf[b,o,f] = Σ_i Xf[b,i,f] · Σ_m Gf[m,f]·W3[m,o*64+i]    (Kf never stored)
// k45: grid 129x4 (k-quarters, 3 CTAs/SM), 4-deep per-warp cp.async pipeline,
// W3 in float4 fragment-pair order (LDS.128 B loads).
// ============================================================================

#define LL     2048
#define NFFT   4096
#define HID    128
#define NBINS  2049   // NFFT/2 + 1

__device__ float  d_h2T[HID * LL];          // [m][l]
__device__ float4 d_W3f4[64 * 8 * 8 * 32];  // [i][warp][kc2][lane] frag quads
__device__ float2 d_tw4[NFFT];
__device__ float2 d_Gf[HID * NFFT];         // [m][f] tf32-rounded, mirrored
__device__ float2 d_Xf[128 * NFFT];         // [b*64+i][f], mirrored
__device__ float2 d_OutfP[4][128 * NBINS];  // per-k-quarter partials

__device__ __forceinline__ float to_tf32(float x) {
    unsigned u;
    asm("cvt.rna.tf32.f32 %0, %1;" : "=r"(u) : "f"(x));
    return __uint_as_float(u);
}

// ---------------- setup: twiddles + W3 fragment-quad repack (tf32) ---------
// d_W3f4[((i*8+w)*8+kc2)*32 + lane] =
//   ( W3[(2*kc2*8+tg)*4096 + col], W3[(2*kc2*8+tg+4)*4096 + col],
//     W3[((2*kc2+1)*8+tg)*4096 + col], W3[((2*kc2+1)*8+tg+4)*4096 + col] )
// with col = (w*8 + (lane>>2))*64 + i, tg = lane&3.
__global__ void setup_kernel(const float* __restrict__ W3) {
    int idx = blockIdx.x * blockDim.x + threadIdx.x;   // < 131072
    if (idx < NFFT) {
        double a = 2.0 * 3.14159265358979323846 * (double)idx / (double)NFFT;
        d_tw4[idx] = make_float2((float)cos(a), (float)(-sin(a)));
    }
    int lane = idx & 31;
    int kc2  = (idx >> 5) & 7;
    int w    = (idx >> 8) & 7;
    int i    = idx >> 11;
    int tg = lane & 3, g = lane >> 2;
    int col = (w * 8 + g) * 64 + i;
    int mA  = (2 * kc2) * 8 + tg;
    int mB  = (2 * kc2 + 1) * 8 + tg;
    d_W3f4[idx] = make_float4(to_tf32(W3[mA * 4096 + col]),
                              to_tf32(W3[(mA + 4) * 4096 + col]),
                              to_tf32(W3[mB * 4096 + col]),
                              to_tf32(W3[(mB + 4) * 4096 + col]));
}

// ------------------------------------------------------------ SIREN stages --
__global__ void gen_h2_kernel(const float* __restrict__ W1,
                              const float* __restrict__ W2) {
    int l = blockIdx.x;
    int j = threadIdx.x;
    __shared__ float h1[HID];
    float rel = -1.0f + 2.0f * (float)l / 2047.0f;
    h1[j] = sinf(30.0f * rel * W1[j]);
    __syncthreads();
    float acc = 0.0f;
#pragma unroll 16
    for (int m = 0; m < HID; m++)
        acc += h1[m] * W2[m * HID + j];
    d_h2T[j * LL + l] = sinf(30.0f * acc);
}

// ------------------------------------------------------- radix-4 FFT core --
__device__ __forceinline__ int rev4(int d) {
    int r = __brev(d) >> 20;
    return ((r & 0x555) << 1) | ((r & 0xAAA) >> 1);
}
__device__ __forceinline__ float2 cmul(float2 a, float2 b) {
    return make_float2(a.x * b.x - a.y * b.y, a.x * b.y + a.y * b.x);
}
__device__ __forceinline__ void fft4_core(float2* buf) {
#pragma unroll
    for (int st = 0; st < 6; st++) {
        int q = 1 << (2 * st);
        int tstep = NFFT >> (2 * st + 2);
        __syncthreads();
#pragma unroll
        for (int k = 0; k < 2; k++) {
            int bf = threadIdx.x + (k << 9);
            int j  = bf & (q - 1);
            int i0 = ((bf >> (2 * st)) << (2 * st + 2)) + j;
            float2 x0 = buf[i0];
            float2 x1 = buf[i0 + q];
            float2 x2 = buf[i0 + 2 * q];
            float2 x3 = buf[i0 + 3 * q];
            float2 u1 = cmul(x1, d_tw4[j * tstep]);
            float2 u2 = cmul(x2, d_tw4[2 * j * tstep]);
            float2 u3 = cmul(x3, d_tw4[3 * j * tstep]);
            float2 a  = make_float2(x0.x + u2.x, x0.y + u2.y);
            float2 b  = make_float2(x0.x - u2.x, x0.y - u2.y);
            float2 c  = make_float2(u1.x + u3.x, u1.y + u3.y);
            float2 dd = make_float2(u1.x - u3.x, u1.y - u3.y);
            buf[i0]         = make_float2(a.x + c.x,  a.y + c.y);
            buf[i0 + q]     = make_float2(b.x + dd.y, b.y - dd.x);
            buf[i0 + 2 * q] = make_float2(a.x - c.x,  a.y - c.y);
            buf[i0 + 3 * q] = make_float2(b.x - dd.y, b.y + dd.x);
        }
    }
    __syncthreads();
}

// ---------------------------- forward FFTs, two real rows packed per block --
__global__ void fft_gx_kernel(const float* __restrict__ x) {
    __shared__ float2 buf[NFFT];
    int blk = blockIdx.x;
    bool isg = blk < 64;
    int r0 = isg ? 2 * blk : 2 * (blk - 64);
    for (int d = threadIdx.x; d < NFFT; d += 512) {
        int src = rev4(d);
        float va = 0.0f, vb = 0.0f;
        if (src < LL) {
            if (isg) {
                va = d_h2T[r0 * LL + (LL - 1 - src)];
                vb = d_h2T[(r0 + 1) * LL + (LL - 1 - src)];
            } else {
                va = x[r0 * LL + src];
                vb = x[(r0 + 1) * LL + src];
            }
        }
        buf[d] = make_float2(va, vb);
    }
    fft4_core(buf);
    for (int f = threadIdx.x; f <= 2048; f += 512) {
        float2 Zf = buf[f];
        float2 Zc = buf[(NFFT - f) & (NFFT - 1)];
        float2 A = make_float2((Zf.x + Zc.x) * 0.5f, (Zf.y - Zc.y) * 0.5f);
        float2 B = make_float2((Zf.y + Zc.y) * 0.5f, (Zc.x - Zf.x) * 0.5f);
        if (isg) {
            A = make_float2(to_tf32(A.x), to_tf32(A.y));
            B = make_float2(to_tf32(B.x), to_tf32(B.y));
            d_Gf[r0 * NFFT + f]       = A;
            d_Gf[(r0 + 1) * NFFT + f] = B;
            if (f > 0 && f < 2048) {
                d_Gf[r0 * NFFT + NFFT - f]       = make_float2(A.x, -A.y);
                d_Gf[(r0 + 1) * NFFT + NFFT - f] = make_float2(B.x, -B.y);
            }
        } else {
            d_Xf[r0 * NFFT + f]       = A;
            d_Xf[(r0 + 1) * NFFT + f] = B;
            if (f > 0 && f < 2048) {
                d_Xf[r0 * NFFT + NFFT - f]       = make_float2(A.x, -A.y);
                d_Xf[(r0 + 1) * NFFT + NFFT - f] = make_float2(B.x, -B.y);
            }
        }
    }
}

// ----------------------- k45: fused kernel-spectrum GEMM + per-bin mixing --
#define MMA_TF32(C, A, B0, B1)                                              \
    asm volatile("mma.sync.aligned.m16n8k8.row.col.f32.tf32.tf32.f32 "      \
        "{%0,%1,%2,%3}, {%4,%5,%6,%7}, {%8,%9}, {%0,%1,%2,%3};"             \
        : "+f"(C[0]), "+f"(C[1]), "+f"(C[2]), "+f"(C[3])                    \
        : "r"(A[0]), "r"(A[1]), "r"(A[2]), "r"(A[3]), "r"(B0), "r"(B1))

#define CP16(dst_u32, src_ptr)                                              \
    asm volatile("cp.async.cg.shared.global [%0], [%1], 16;"                \
                 :: "r"(dst_u32), "l"(src_ptr))

// smem: Xs [128][16] float2 (16 KB) + 8 warps x 4 bufs x 64 float4 (32 KB)
#define XS_FLOATS   (128 * 16 * 2)
#define SLICE_F4    64                          // float4 per buffer (1 KB)
#define K45_SMEM    (XS_FLOATS * 4 + 8 * 4 * SLICE_F4 * 16)

__global__ void __launch_bounds__(256, 3) k45_kernel() {
    extern __shared__ float smem[];
    float2* Xs = (float2*)smem;

    const int f0   = blockIdx.x * 16;           // 129 f-tiles
    const int kq   = blockIdx.y;                // k-quarter 0..3
    const int kofs = kq * 32;
    const int tid  = threadIdx.x;
    const int lane = tid & 31;
    const int warp = tid >> 5;
    const int g    = lane >> 2;
    const int tg   = lane & 3;
    const int obase = warp * 8;

    float4* Bw = (float4*)(smem + XS_FLOATS) + warp * (4 * SLICE_F4);
    unsigned bw_base = (unsigned)__cvta_generic_to_shared(Bw);

    // per-warp slice: d_W3f4[((i*8+warp)*8 + kq*2) * 32 ... +64] float4 (1 KB)
#define LOAD_SLICE(i_, buf_)                                                \
    {                                                                       \
        const float4* srcb = d_W3f4 + (((i_) * 8 + warp) * 8 + kq * 2) * 32;\
        unsigned dstb = bw_base + (buf_) * (SLICE_F4 * 16);                 \
        CP16(dstb + lane * 16, srcb + lane);                                \
        CP16(dstb + (lane + 32) * 16, srcb + lane + 32);                    \
    }

    LOAD_SLICE(0, 0); asm volatile("cp.async.commit_group;");
    LOAD_SLICE(1, 1); asm volatile("cp.async.commit_group;");
    LOAD_SLICE(2, 2); asm volatile("cp.async.commit_group;");

    for (int idx = tid; idx < 128 * 16; idx += 256) {
        int row = idx >> 4, ff = idx & 15;
        Xs[idx] = d_Xf[row * NFFT + f0 + ff];
    }

    // Hoist A fragments (Gf, complex) for this k-quarter: 4 steps, 32 regs.
    unsigned aR[4][4], aI[4][4];
#pragma unroll
    for (int k0 = 0; k0 < 4; k0++) {
        int kk = kofs + k0 * 8;
        float2 v0 = d_Gf[(kk + tg)     * NFFT + f0 + g];
        float2 v1 = d_Gf[(kk + tg)     * NFFT + f0 + g + 8];
        float2 v2 = d_Gf[(kk + tg + 4) * NFFT + f0 + g];
        float2 v3 = d_Gf[(kk + tg + 4) * NFFT + f0 + g + 8];
        aR[k0][0] = __float_as_uint(v0.x); aI[k0][0] = __float_as_uint(v0.y);
        aR[k0][1] = __float_as_uint(v1.x); aI[k0][1] = __float_as_uint(v1.y);
        aR[k0][2] = __float_as_uint(v2.x); aI[k0][2] = __float_as_uint(v2.y);
        aR[k0][3] = __float_as_uint(v3.x); aI[k0][3] = __float_as_uint(v3.y);
    }

    float oR[2][2][2] = {}, oI[2][2][2] = {};

    __syncthreads();     // Xs visible; last block-wide barrier.

    for (int i = 0; i < 64; i++) {
        if (i + 3 < 64) LOAD_SLICE(i + 3, (i + 3) & 3);
        asm volatile("cp.async.commit_group;");      // real or empty group
        asm volatile("cp.async.wait_group 3;");      // slice i is ready
        __syncwarp();

        const float4* Bp = Bw + (i & 3) * SLICE_F4 + lane;
        float4 bv0 = Bp[0];       // k-steps 0,1: (b0,b1),(b2,b3)
        float4 bv1 = Bp[32];      // k-steps 2,3
        float cR0[4] = {0,0,0,0}, cR1[4] = {0,0,0,0};
        float cI0[4] = {0,0,0,0}, cI1[4] = {0,0,0,0};
        {
            unsigned b0 = __float_as_uint(bv0.x), b1 = __float_as_uint(bv0.y);
            unsigned b2 = __float_as_uint(bv0.z), b3 = __float_as_uint(bv0.w);
            MMA_TF32(cR0, aR[0], b0, b1);
            MMA_TF32(cI0, aI[0], b0, b1);
            MMA_TF32(cR1, aR[1], b2, b3);
            MMA_TF32(cI1, aI[1], b2, b3);
        }
        {
            unsigned b0 = __float_as_uint(bv1.x), b1 = __float_as_uint(bv1.y);
            unsigned b2 = __float_as_uint(bv1.z), b3 = __float_as_uint(bv1.w);
            MMA_TF32(cR0, aR[2], b0, b1);
            MMA_TF32(cI0, aI[2], b0, b1);
            MMA_TF32(cR1, aR[3], b2, b3);
            MMA_TF32(cI1, aI[3], b2, b3);
        }
#pragma unroll
        for (int rr = 0; rr < 2; rr++) {
            int flocal = g + rr * 8;
#pragma unroll
            for (int b = 0; b < 2; b++) {
                float2 xv = Xs[(b * 64 + i) * 16 + flocal];
#pragma unroll
                for (int cc = 0; cc < 2; cc++) {
                    float kr = cR0[rr * 2 + cc] + cR1[rr * 2 + cc];
                    float ki = cI0[rr * 2 + cc] + cI1[rr * 2 + cc];
                    oR[b][rr][cc] += xv.x * kr - xv.y * ki;
                    oI[b][rr][cc] += xv.x * ki + xv.y * kr;
                }
            }
        }
    }

#pragma unroll
    for (int rr = 0; rr < 2; rr++) {
        int f = f0 + g + rr * 8;
        if (f < NBINS) {
#pragma unroll
            for (int b = 0; b < 2; b++)
#pragma unroll
                for (int cc = 0; cc < 2; cc++) {
                    int o = obase + tg * 2 + cc;
                    d_OutfP[kq][(b * 64 + o) * NBINS + f] =
                        make_float2(oR[b][rr][cc], oI[b][rr][cc]);
                }
        }
    }
}

// ---------------- inverse FFT: sums k-quarter partials, 2 rows per block ---
__global__ void fft_inv_kernel(float* __restrict__ out) {
    __shared__ float2 buf[NFFT];
    int t0 = 2 * blockIdx.x;
    for (int d = threadIdx.x; d < NFFT; d += 512) {
        int src = rev4(d);
        int s = (src <= 2048) ? src : (NFFT - src);
        float2 a = make_float2(0.f, 0.f), b = make_float2(0.f, 0.f);
#pragma unroll
        for (int p = 0; p < 4; p++) {
            float2 va = d_OutfP[p][(size_t)t0 * NBINS + s];
            float2 vb = d_OutfP[p][(size_t)(t0 + 1) * NBINS + s];
            a.x += va.x; a.y += va.y;
            b.x += vb.x; b.y += vb.y;
        }
        float2 v;
        if (src <= 2048) v = make_float2(a.x - b.y, -a.y - b.x);
        else             v = make_float2(a.x + b.y,  a.y - b.x);
        buf[d] = v;
    }
    fft4_core(buf);
    const float inv = 1.0f / (float)NFFT;
    for (int n = threadIdx.x; n < LL; n += 512) {
        out[t0 * LL + n]       =  buf[n].x * inv;
        out[(t0 + 1) * LL + n] = -buf[n].y * inv;
    }
}

// ============================================================================
extern "C" void kernel_launch(void* const* d_in, const int* in_sizes, int n_in,
                              void* d_out, int out_size) {
    (void)in_sizes; (void)n_in; (void)out_size;
    const float* x  = (const float*)d_in[0];
    const float* W1 = (const float*)d_in[1];
    const float* W2 = (const float*)d_in[2];
    const float* W3 = (const float*)d_in[3];
    float* out = (float*)d_out;

    cudaFuncSetAttribute(k45_kernel,
                         cudaFuncAttributeMaxDynamicSharedMemorySize, K45_SMEM);

    setup_kernel<<<512, 256>>>(W3);
    gen_h2_kernel<<<2048, 128>>>(W1, W2);
    fft_gx_kernel<<<128, 512>>>(x);
    k45_kernel<<<dim3(129, 4), 256, K45_SMEM>>>();
    fft_inv_kernel<<<64, 512>>>(out);
}

// round 10
// speedup vs baseline: 1.2627x; 1.2627x over previous
#include <cuda_runtime.h>
#include <math.h>

// ============================================================================
// CKConv via FFT convolution, fused tf32 tensor-core spectrum GEMM.
//   Outf[b,o,f] = Σ_i Xf[b,i,f] · Σ_m Gf[m,f]·W3[m,o*64+i]    (Kf never stored)
// k45: grid 129x2 (k-halves, 2 CTAs/SM), 4-deep per-warp cp.async pipeline,
// float4 fragment quads (LDS.128), phase-buffered DEFERRED epilogue so the
// MMA->FMA RAW never stalls.
// ============================================================================

#define LL     2048
#define NFFT   4096
#define HID    128
#define NBINS  2049   // NFFT/2 + 1

__device__ float  d_h2T[HID * LL];          // [m][l]
__device__ float4 d_W3f4[64 * 8 * 8 * 32];  // [i][warp][kc2][lane] frag quads
__device__ float2 d_tw4[NFFT];
__device__ float2 d_Gf[HID * NFFT];         // [m][f] tf32-rounded, mirrored
__device__ float2 d_Xf[128 * NFFT];         // [b*64+i][f], mirrored
__device__ float2 d_OutfP[2][128 * NBINS];  // per-k-half partials

__device__ __forceinline__ float to_tf32(float x) {
    unsigned u;
    asm("cvt.rna.tf32.f32 %0, %1;" : "=r"(u) : "f"(x));
    return __uint_as_float(u);
}

// ---------------- setup: twiddles + W3 fragment-quad repack (tf32) ---------
__global__ void setup_kernel(const float* __restrict__ W3) {
    int idx = blockIdx.x * blockDim.x + threadIdx.x;   // < 131072
    if (idx < NFFT) {
        double a = 2.0 * 3.14159265358979323846 * (double)idx / (double)NFFT;
        d_tw4[idx] = make_float2((float)cos(a), (float)(-sin(a)));
    }
    int lane = idx & 31;
    int kc2  = (idx >> 5) & 7;
    int w    = (idx >> 8) & 7;
    int i    = idx >> 11;
    int tg = lane & 3, g = lane >> 2;
    int col = (w * 8 + g) * 64 + i;
    int mA  = (2 * kc2) * 8 + tg;
    int mB  = (2 * kc2 + 1) * 8 + tg;
    d_W3f4[idx] = make_float4(to_tf32(W3[mA * 4096 + col]),
                              to_tf32(W3[(mA + 4) * 4096 + col]),
                              to_tf32(W3[mB * 4096 + col]),
                              to_tf32(W3[(mB + 4) * 4096 + col]));
}

// ------------------------------------------------------------ SIREN stages --
__global__ void gen_h2_kernel(const float* __restrict__ W1,
                              const float* __restrict__ W2) {
    int l = blockIdx.x;
    int j = threadIdx.x;
    __shared__ float h1[HID];
    float rel = -1.0f + 2.0f * (float)l / 2047.0f;
    h1[j] = sinf(30.0f * rel * W1[j]);
    __syncthreads();
    float acc = 0.0f;
#pragma unroll 16
    for (int m = 0; m < HID; m++)
        acc += h1[m] * W2[m * HID + j];
    d_h2T[j * LL + l] = sinf(30.0f * acc);
}

// ------------------------------------------------------- radix-4 FFT core --
__device__ __forceinline__ int rev4(int d) {
    int r = __brev(d) >> 20;
    return ((r & 0x555) << 1) | ((r & 0xAAA) >> 1);
}
__device__ __forceinline__ float2 cmul(float2 a, float2 b) {
    return make_float2(a.x * b.x - a.y * b.y, a.x * b.y + a.y * b.x);
}
__device__ __forceinline__ void fft4_core(float2* buf) {
#pragma unroll
    for (int st = 0; st < 6; st++) {
        int q = 1 << (2 * st);
        int tstep = NFFT >> (2 * st + 2);
        __syncthreads();
#pragma unroll
        for (int k = 0; k < 2; k++) {
            int bf = threadIdx.x + (k << 9);
            int j  = bf & (q - 1);
            int i0 = ((bf >> (2 * st)) << (2 * st + 2)) + j;
            float2 x0 = buf[i0];
            float2 x1 = buf[i0 + q];
            float2 x2 = buf[i0 + 2 * q];
            float2 x3 = buf[i0 + 3 * q];
            float2 u1 = cmul(x1, d_tw4[j * tstep]);
            float2 u2 = cmul(x2, d_tw4[2 * j * tstep]);
            float2 u3 = cmul(x3, d_tw4[3 * j * tstep]);
            float2 a  = make_float2(x0.x + u2.x, x0.y + u2.y);
            float2 b  = make_float2(x0.x - u2.x, x0.y - u2.y);
            float2 c  = make_float2(u1.x + u3.x, u1.y + u3.y);
            float2 dd = make_float2(u1.x - u3.x, u1.y - u3.y);
            buf[i0]         = make_float2(a.x + c.x,  a.y + c.y);
            buf[i0 + q]     = make_float2(b.x + dd.y, b.y - dd.x);
            buf[i0 + 2 * q] = make_float2(a.x - c.x,  a.y - c.y);
            buf[i0 + 3 * q] = make_float2(b.x - dd.y, b.y + dd.x);
        }
    }
    __syncthreads();
}

// ---------------------------- forward FFTs, two real rows packed per block --
__global__ void fft_gx_kernel(const float* __restrict__ x) {
    __shared__ float2 buf[NFFT];
    int blk = blockIdx.x;
    bool isg = blk < 64;
    int r0 = isg ? 2 * blk : 2 * (blk - 64);
    for (int d = threadIdx.x; d < NFFT; d += 512) {
        int src = rev4(d);
        float va = 0.0f, vb = 0.0f;
        if (src < LL) {
            if (isg) {
                va = d_h2T[r0 * LL + (LL - 1 - src)];
                vb = d_h2T[(r0 + 1) * LL + (LL - 1 - src)];
            } else {
                va = x[r0 * LL + src];
                vb = x[(r0 + 1) * LL + src];
            }
        }
        buf[d] = make_float2(va, vb);
    }
    fft4_core(buf);
    for (int f = threadIdx.x; f <= 2048; f += 512) {
        float2 Zf = buf[f];
        float2 Zc = buf[(NFFT - f) & (NFFT - 1)];
        float2 A = make_float2((Zf.x + Zc.x) * 0.5f, (Zf.y - Zc.y) * 0.5f);
        float2 B = make_float2((Zf.y + Zc.y) * 0.5f, (Zc.x - Zf.x) * 0.5f);
        if (isg) {
            A = make_float2(to_tf32(A.x), to_tf32(A.y));
            B = make_float2(to_tf32(B.x), to_tf32(B.y));
            d_Gf[r0 * NFFT + f]       = A;
            d_Gf[(r0 + 1) * NFFT + f] = B;
            if (f > 0 && f < 2048) {
                d_Gf[r0 * NFFT + NFFT - f]       = make_float2(A.x, -A.y);
                d_Gf[(r0 + 1) * NFFT + NFFT - f] = make_float2(B.x, -B.y);
            }
        } else {
            d_Xf[r0 * NFFT + f]       = A;
            d_Xf[(r0 + 1) * NFFT + f] = B;
            if (f > 0 && f < 2048) {
                d_Xf[r0 * NFFT + NFFT - f]       = make_float2(A.x, -A.y);
                d_Xf[(r0 + 1) * NFFT + NFFT - f] = make_float2(B.x, -B.y);
            }
        }
    }
}

// ----------------------- k45: fused kernel-spectrum GEMM + per-bin mixing --
#define MMA_TF32(C, A, B0, B1)                                              \
    asm volatile("mma.sync.aligned.m16n8k8.row.col.f32.tf32.tf32.f32 "      \
        "{%0,%1,%2,%3}, {%4,%5,%6,%7}, {%8,%9}, {%0,%1,%2,%3};"             \
        : "+f"(C[0]), "+f"(C[1]), "+f"(C[2]), "+f"(C[3])                    \
        : "r"(A[0]), "r"(A[1]), "r"(A[2]), "r"(A[3]), "r"(B0), "r"(B1))

#define CP16(dst_u32, src_ptr)                                              \
    asm volatile("cp.async.cg.shared.global [%0], [%1], 16;"                \
                 :: "r"(dst_u32), "l"(src_ptr))

// smem: Xs [128][16] float2 (16 KB) + 8 warps x 4 bufs x 128 float4 (64 KB)
#define XS_FLOATS   (128 * 16 * 2)
#define SLICE_F4    128                         // float4 per buffer (2 KB)
#define K45_SMEM    (XS_FLOATS * 4 + 8 * 4 * SLICE_F4 * 16)

__global__ void __launch_bounds__(256, 2) k45_kernel() {
    extern __shared__ float smem[];
    float2* Xs = (float2*)smem;

    const int f0   = blockIdx.x * 16;           // 129 f-tiles
    const int kh   = blockIdx.y;                // k-half 0..1
    const int kofs = kh * 64;
    const int tid  = threadIdx.x;
    const int lane = tid & 31;
    const int warp = tid >> 5;
    const int g    = lane >> 2;
    const int tg   = lane & 3;
    const int obase = warp * 8;

    float4* Bw = (float4*)(smem + XS_FLOATS) + warp * (4 * SLICE_F4);
    unsigned bw_base = (unsigned)__cvta_generic_to_shared(Bw);

    // per-warp slice: d_W3f4[((i*8+warp)*8 + kh*4) * 32 ... +128] float4 (2 KB)
#define LOAD_SLICE(i_, buf_)                                                \
    {                                                                       \
        const float4* srcb = d_W3f4 + (((i_) * 8 + warp) * 8 + kh * 4) * 32;\
        unsigned dstb = bw_base + (buf_) * (SLICE_F4 * 16);                 \
        _Pragma("unroll")                                                   \
        for (int j = 0; j < 4; j++)                                         \
            CP16(dstb + (lane + (j << 5)) * 16, srcb + lane + (j << 5));    \
    }

    LOAD_SLICE(0, 0); asm volatile("cp.async.commit_group;");
    LOAD_SLICE(1, 1); asm volatile("cp.async.commit_group;");
    LOAD_SLICE(2, 2); asm volatile("cp.async.commit_group;");

    for (int idx = tid; idx < 128 * 16; idx += 256) {
        int row = idx >> 4, ff = idx & 15;
        Xs[idx] = d_Xf[row * NFFT + f0 + ff];
    }

    // Hoist A fragments (Gf, complex) for this k-half: 8 steps, 64 regs.
    unsigned aR[8][4], aI[8][4];
#pragma unroll
    for (int k0 = 0; k0 < 8; k0++) {
        int kk = kofs + k0 * 8;
        float2 v0 = d_Gf[(kk + tg)     * NFFT + f0 + g];
        float2 v1 = d_Gf[(kk + tg)     * NFFT + f0 + g + 8];
        float2 v2 = d_Gf[(kk + tg + 4) * NFFT + f0 + g];
        float2 v3 = d_Gf[(kk + tg + 4) * NFFT + f0 + g + 8];
        aR[k0][0] = __float_as_uint(v0.x); aI[k0][0] = __float_as_uint(v0.y);
        aR[k0][1] = __float_as_uint(v1.x); aI[k0][1] = __float_as_uint(v1.y);
        aR[k0][2] = __float_as_uint(v2.x); aI[k0][2] = __float_as_uint(v2.y);
        aR[k0][3] = __float_as_uint(v3.x); aI[k0][3] = __float_as_uint(v3.y);
    }

    float oR[2][2][2] = {}, oI[2][2][2] = {};
    float cR[2][4], cI[2][4];               // phase-buffered accumulators

    __syncthreads();     // Xs visible; last block-wide barrier.

#pragma unroll 2
    for (int i = 0; i < 64; i++) {
        const int p = i & 1;
        if (i + 3 < 64) LOAD_SLICE(i + 3, (i + 3) & 3);
        asm volatile("cp.async.commit_group;");      // real or empty group
        asm volatile("cp.async.wait_group 3;");      // slice i is ready
        __syncwarp();

        // ---- issue this iteration's MMAs into phase p ----
        const float4* Bp = Bw + (i & 3) * SLICE_F4 + lane;
#pragma unroll
        for (int j = 0; j < 4; j++) { cR[p][j] = 0.f; cI[p][j] = 0.f; }
#pragma unroll
        for (int q = 0; q < 4; q++) {
            float4 bv = Bp[q * 32];
            unsigned b0 = __float_as_uint(bv.x), b1 = __float_as_uint(bv.y);
            unsigned b2 = __float_as_uint(bv.z), b3 = __float_as_uint(bv.w);
            MMA_TF32(cR[p], aR[2 * q],     b0, b1);
            MMA_TF32(cI[p], aI[2 * q],     b0, b1);
            MMA_TF32(cR[p], aR[2 * q + 1], b2, b3);
            MMA_TF32(cI[p], aI[2 * q + 1], b2, b3);
        }

        // ---- deferred epilogue for iteration i-1 (phase p^1) ----
        if (i > 0) {
            const int ip = i - 1, pp = p ^ 1;
#pragma unroll
            for (int rr = 0; rr < 2; rr++) {
                int flocal = g + rr * 8;
#pragma unroll
                for (int b = 0; b < 2; b++) {
                    float2 xv = Xs[(b * 64 + ip) * 16 + flocal];
#pragma unroll
                    for (int cc = 0; cc < 2; cc++) {
                        float kr = cR[pp][rr * 2 + cc];
                        float ki = cI[pp][rr * 2 + cc];
                        oR[b][rr][cc] += xv.x * kr - xv.y * ki;
                        oI[b][rr][cc] += xv.x * ki + xv.y * kr;
                    }
                }
            }
        }
    }
    // final epilogue: iteration 63 lives in phase 1
    {
        const int ip = 63, pp = 1;
#pragma unroll
        for (int rr = 0; rr < 2; rr++) {
            int flocal = g + rr * 8;
#pragma unroll
            for (int b = 0; b < 2; b++) {
                float2 xv = Xs[(b * 64 + ip) * 16 + flocal];
#pragma unroll
                for (int cc = 0; cc < 2; cc++) {
                    float kr = cR[pp][rr * 2 + cc];
                    float ki = cI[pp][rr * 2 + cc];
                    oR[b][rr][cc] += xv.x * kr - xv.y * ki;
                    oI[b][rr][cc] += xv.x * ki + xv.y * kr;
                }
            }
        }
    }

#pragma unroll
    for (int rr = 0; rr < 2; rr++) {
        int f = f0 + g + rr * 8;
        if (f < NBINS) {
#pragma unroll
            for (int b = 0; b < 2; b++)
#pragma unroll
                for (int cc = 0; cc < 2; cc++) {
                    int o = obase + tg * 2 + cc;
                    d_OutfP[kh][(b * 64 + o) * NBINS + f] =
                        make_float2(oR[b][rr][cc], oI[b][rr][cc]);
                }
        }
    }
}

// ---------------- inverse FFT: sums k-half partials, 2 rows per block ------
__global__ void fft_inv_kernel(float* __restrict__ out) {
    __shared__ float2 buf[NFFT];
    int t0 = 2 * blockIdx.x;
    const float2* P00 = d_OutfP[0] + (size_t)t0 * NBINS;
    const float2* P01 = d_OutfP[1] + (size_t)t0 * NBINS;
    const float2* P10 = d_OutfP[0] + (size_t)(t0 + 1) * NBINS;
    const float2* P11 = d_OutfP[1] + (size_t)(t0 + 1) * NBINS;
    for (int d = threadIdx.x; d < NFFT; d += 512) {
        int src = rev4(d);
        int s = (src <= 2048) ? src : (NFFT - src);
        float2 a = make_float2(P00[s].x + P01[s].x, P00[s].y + P01[s].y);
        float2 b = make_float2(P10[s].x + P11[s].x, P10[s].y + P11[s].y);
        float2 v;
        if (src <= 2048) v = make_float2(a.x - b.y, -a.y - b.x);
        else             v = make_float2(a.x + b.y,  a.y - b.x);
        buf[d] = v;
    }
    fft4_core(buf);
    const float inv = 1.0f / (float)NFFT;
    for (int n = threadIdx.x; n < LL; n += 512) {
        out[t0 * LL + n]       =  buf[n].x * inv;
        out[(t0 + 1) * LL + n] = -buf[n].y * inv;
    }
}

// ============================================================================
extern "C" void kernel_launch(void* const* d_in, const int* in_sizes, int n_in,
                              void* d_out, int out_size) {
    (void)in_sizes; (void)n_in; (void)out_size;
    const float* x  = (const float*)d_in[0];
    const float* W1 = (const float*)d_in[1];
    const float* W2 = (const float*)d_in[2];
    const float* W3 = (const float*)d_in[3];
    float* out = (float*)d_out;

    cudaFuncSetAttribute(k45_kernel,
                         cudaFuncAttributeMaxDynamicSharedMemorySize, K45_SMEM);

    setup_kernel<<<512, 256>>>(W3);
    gen_h2_kernel<<<2048, 128>>>(W1, W2);
    fft_gx_kernel<<<128, 512>>>(x);
    k45_kernel<<<dim3(129, 2), 256, K45_SMEM>>>();
    fft_inv_kernel<<<64, 512>>>(out);
}

// round 11
// speedup vs baseline: 1.2941x; 1.0249x over previous
#include <cuda_runtime.h>
#include <math.h>

// ============================================================================
// CKConv via FFT convolution, fused tf32 tensor-core spectrum GEMM.
//   Outf[b,o,f] = Σ_i Xf[b,i,f] · Σ_m Gf[m,f]·W3[m,o*64+i]    (Kf never stored)
// Radix-8 FFTs (4 stages). k45 unchanged from R10 (phase-buffered epilogue).
// ============================================================================

#define LL     2048
#define NFFT   4096
#define HID    128
#define NBINS  2049   // NFFT/2 + 1

__device__ float  d_h2T[HID * LL];          // [m][l]
__device__ float4 d_W3f4[64 * 8 * 8 * 32];  // [i][warp][kc2][lane] frag quads
__device__ float2 d_tw4[NFFT];
__device__ float2 d_Gf[HID * NFFT];         // [m][f] tf32-rounded, mirrored
__device__ float2 d_Xf[128 * NFFT];         // [b*64+i][f], mirrored
__device__ float2 d_OutfP[2][128 * NBINS];  // per-k-half partials

__device__ __forceinline__ float to_tf32(float x) {
    unsigned u;
    asm("cvt.rna.tf32.f32 %0, %1;" : "=r"(u) : "f"(x));
    return __uint_as_float(u);
}

// -------------- fused: SIREN h2 + twiddles + W3 fragment repack ------------
__global__ void setup_h2_kernel(const float* __restrict__ W1,
                                const float* __restrict__ W2,
                                const float* __restrict__ W3) {
    __shared__ float h1[HID];
    const int tid = threadIdx.x;
    const int l   = blockIdx.x;     // 0..2047

    if (tid < HID) {
        float rel = -1.0f + 2.0f * (float)l / 2047.0f;
        h1[tid] = sinf(30.0f * rel * W1[tid]);
    }
    __syncthreads();
    if (tid < HID) {
        float acc = 0.0f;
#pragma unroll 16
        for (int m = 0; m < HID; m++)
            acc += h1[m] * W2[m * HID + tid];
        d_h2T[tid * LL + l] = sinf(30.0f * acc);
    } else if (tid < HID + 64) {
        int idx = blockIdx.x * 64 + (tid - HID);   // 0..131071
        if (idx < NFFT) {
            double a = 2.0 * 3.14159265358979323846 * (double)idx / (double)NFFT;
            d_tw4[idx] = make_float2((float)cos(a), (float)(-sin(a)));
        }
        int lane = idx & 31;
        int kc2  = (idx >> 5) & 7;
        int w    = (idx >> 8) & 7;
        int i    = idx >> 11;
        int tg = lane & 3, g = lane >> 2;
        int col = (w * 8 + g) * 64 + i;
        int mA  = (2 * kc2) * 8 + tg;
        int mB  = (2 * kc2 + 1) * 8 + tg;
        d_W3f4[idx] = make_float4(to_tf32(W3[mA * 4096 + col]),
                                  to_tf32(W3[(mA + 4) * 4096 + col]),
                                  to_tf32(W3[mB * 4096 + col]),
                                  to_tf32(W3[(mB + 4) * 4096 + col]));
    }
}

// ------------------------------------------------------- radix-8 FFT core --
__device__ __forceinline__ int rev8(int d) {   // reverse 4 octal digits
    return ((d & 7) << 9) | (((d >> 3) & 7) << 6) |
           (((d >> 6) & 7) << 3) | ((d >> 9) & 7);
}
__device__ __forceinline__ float2 cmul(float2 a, float2 b) {
    return make_float2(a.x * b.x - a.y * b.y, a.x * b.y + a.y * b.x);
}

#define SQRT1_2 0.70710678118654752f

// 4 stages, 512 threads, one radix-8 butterfly per thread per stage.
__device__ __forceinline__ void fft8_core(float2* buf) {
#pragma unroll
    for (int st = 0; st < 4; st++) {
        const int q = 1 << (3 * st);
        const int tstep = NFFT >> (3 * st + 3);
        __syncthreads();
        const int bf = threadIdx.x;                // 0..511
        const int j  = bf & (q - 1);
        const int base = ((bf >> (3 * st)) << (3 * st + 3)) + j;

        float2 u[8];
        u[0] = buf[base];
#pragma unroll
        for (int t = 1; t < 8; t++) {
            float2 v = buf[base + t * q];
            u[t] = (st == 0) ? v : cmul(v, d_tw4[j * t * tstep]);
        }
        // even radix-4: (u0,u2,u4,u6) -> E0..E3
        float2 ea = make_float2(u[0].x + u[4].x, u[0].y + u[4].y);
        float2 eb = make_float2(u[0].x - u[4].x, u[0].y - u[4].y);
        float2 ec = make_float2(u[2].x + u[6].x, u[2].y + u[6].y);
        float2 ed = make_float2(u[2].x - u[6].x, u[2].y - u[6].y);
        float2 E0 = make_float2(ea.x + ec.x, ea.y + ec.y);
        float2 E1 = make_float2(eb.x + ed.y, eb.y - ed.x);
        float2 E2 = make_float2(ea.x - ec.x, ea.y - ec.y);
        float2 E3 = make_float2(eb.x - ed.y, eb.y + ed.x);
        // odd radix-4: (u1,u3,u5,u7) -> O0..O3
        float2 oa = make_float2(u[1].x + u[5].x, u[1].y + u[5].y);
        float2 ob = make_float2(u[1].x - u[5].x, u[1].y - u[5].y);
        float2 oc = make_float2(u[3].x + u[7].x, u[3].y + u[7].y);
        float2 od = make_float2(u[3].x - u[7].x, u[3].y - u[7].y);
        float2 O0 = make_float2(oa.x + oc.x, oa.y + oc.y);
        float2 O1 = make_float2(ob.x + od.y, ob.y - od.x);
        float2 O2 = make_float2(oa.x - oc.x, oa.y - oc.y);
        float2 O3 = make_float2(ob.x - od.y, ob.y + od.x);
        // twist odds: O1*=w8, O2*=-i, O3*=w8^3;  w8 = s(1 - i)
        float2 T1 = make_float2(SQRT1_2 * (O1.x + O1.y), SQRT1_2 * (O1.y - O1.x));
        float2 T2 = make_float2(O2.y, -O2.x);
        float2 T3 = make_float2(SQRT1_2 * (O3.y - O3.x), -SQRT1_2 * (O3.x + O3.y));
        buf[base]         = make_float2(E0.x + O0.x, E0.y + O0.y);
        buf[base + 4 * q] = make_float2(E0.x - O0.x, E0.y - O0.y);
        buf[base + 1 * q] = make_float2(E1.x + T1.x, E1.y + T1.y);
        buf[base + 5 * q] = make_float2(E1.x - T1.x, E1.y - T1.y);
        buf[base + 2 * q] = make_float2(E2.x + T2.x, E2.y + T2.y);
        buf[base + 6 * q] = make_float2(E2.x - T2.x, E2.y - T2.y);
        buf[base + 3 * q] = make_float2(E3.x + T3.x, E3.y + T3.y);
        buf[base + 7 * q] = make_float2(E3.x - T3.x, E3.y - T3.y);
    }
    __syncthreads();
}

// ---------------------------- forward FFTs, two real rows packed per block --
__global__ void fft_gx_kernel(const float* __restrict__ x) {
    __shared__ float2 buf[NFFT];
    int blk = blockIdx.x;
    bool isg = blk < 64;
    int r0 = isg ? 2 * blk : 2 * (blk - 64);
    for (int d = threadIdx.x; d < NFFT; d += 512) {
        int src = rev8(d);
        float va = 0.0f, vb = 0.0f;
        if (src < LL) {
            if (isg) {
                va = d_h2T[r0 * LL + (LL - 1 - src)];
                vb = d_h2T[(r0 + 1) * LL + (LL - 1 - src)];
            } else {
                va = x[r0 * LL + src];
                vb = x[(r0 + 1) * LL + src];
            }
        }
        buf[d] = make_float2(va, vb);
    }
    fft8_core(buf);
    for (int f = threadIdx.x; f <= 2048; f += 512) {
        float2 Zf = buf[f];
        float2 Zc = buf[(NFFT - f) & (NFFT - 1)];
        float2 A = make_float2((Zf.x + Zc.x) * 0.5f, (Zf.y - Zc.y) * 0.5f);
        float2 B = make_float2((Zf.y + Zc.y) * 0.5f, (Zc.x - Zf.x) * 0.5f);
        if (isg) {
            A = make_float2(to_tf32(A.x), to_tf32(A.y));
            B = make_float2(to_tf32(B.x), to_tf32(B.y));
            d_Gf[r0 * NFFT + f]       = A;
            d_Gf[(r0 + 1) * NFFT + f] = B;
            if (f > 0 && f < 2048) {
                d_Gf[r0 * NFFT + NFFT - f]       = make_float2(A.x, -A.y);
                d_Gf[(r0 + 1) * NFFT + NFFT - f] = make_float2(B.x, -B.y);
            }
        } else {
            d_Xf[r0 * NFFT + f]       = A;
            d_Xf[(r0 + 1) * NFFT + f] = B;
            if (f > 0 && f < 2048) {
                d_Xf[r0 * NFFT + NFFT - f]       = make_float2(A.x, -A.y);
                d_Xf[(r0 + 1) * NFFT + NFFT - f] = make_float2(B.x, -B.y);
            }
        }
    }
}

// ----------------------- k45: fused kernel-spectrum GEMM + per-bin mixing --
// (unchanged from R10: 41.6 us)
#define MMA_TF32(C, A, B0, B1)                                              \
    asm volatile("mma.sync.aligned.m16n8k8.row.col.f32.tf32.tf32.f32 "      \
        "{%0,%1,%2,%3}, {%4,%5,%6,%7}, {%8,%9}, {%0,%1,%2,%3};"             \
        : "+f"(C[0]), "+f"(C[1]), "+f"(C[2]), "+f"(C[3])                    \
        : "r"(A[0]), "r"(A[1]), "r"(A[2]), "r"(A[3]), "r"(B0), "r"(B1))

#define CP16(dst_u32, src_ptr)                                              \
    asm volatile("cp.async.cg.shared.global [%0], [%1], 16;"                \
                 :: "r"(dst_u32), "l"(src_ptr))

#define XS_FLOATS   (128 * 16 * 2)
#define SLICE_F4    128
#define K45_SMEM    (XS_FLOATS * 4 + 8 * 4 * SLICE_F4 * 16)

__global__ void __launch_bounds__(256, 2) k45_kernel() {
    extern __shared__ float smem[];
    float2* Xs = (float2*)smem;

    const int f0   = blockIdx.x * 16;
    const int kh   = blockIdx.y;
    const int kofs = kh * 64;
    const int tid  = threadIdx.x;
    const int lane = tid & 31;
    const int warp = tid >> 5;
    const int g    = lane >> 2;
    const int tg   = lane & 3;
    const int obase = warp * 8;

    float4* Bw = (float4*)(smem + XS_FLOATS) + warp * (4 * SLICE_F4);
    unsigned bw_base = (unsigned)__cvta_generic_to_shared(Bw);

#define LOAD_SLICE(i_, buf_)                                                \
    {                                                                       \
        const float4* srcb = d_W3f4 + (((i_) * 8 + warp) * 8 + kh * 4) * 32;\
        unsigned dstb = bw_base + (buf_) * (SLICE_F4 * 16);                 \
        _Pragma("unroll")                                                   \
        for (int j = 0; j < 4; j++)                                         \
            CP16(dstb + (lane + (j << 5)) * 16, srcb + lane + (j << 5));    \
    }

    LOAD_SLICE(0, 0); asm volatile("cp.async.commit_group;");
    LOAD_SLICE(1, 1); asm volatile("cp.async.commit_group;");
    LOAD_SLICE(2, 2); asm volatile("cp.async.commit_group;");

    for (int idx = tid; idx < 128 * 16; idx += 256) {
        int row = idx >> 4, ff = idx & 15;
        Xs[idx] = d_Xf[row * NFFT + f0 + ff];
    }

    unsigned aR[8][4], aI[8][4];
#pragma unroll
    for (int k0 = 0; k0 < 8; k0++) {
        int kk = kofs + k0 * 8;
        float2 v0 = d_Gf[(kk + tg)     * NFFT + f0 + g];
        float2 v1 = d_Gf[(kk + tg)     * NFFT + f0 + g + 8];
        float2 v2 = d_Gf[(kk + tg + 4) * NFFT + f0 + g];
        float2 v3 = d_Gf[(kk + tg + 4) * NFFT + f0 + g + 8];
        aR[k0][0] = __float_as_uint(v0.x); aI[k0][0] = __float_as_uint(v0.y);
        aR[k0][1] = __float_as_uint(v1.x); aI[k0][1] = __float_as_uint(v1.y);
        aR[k0][2] = __float_as_uint(v2.x); aI[k0][2] = __float_as_uint(v2.y);
        aR[k0][3] = __float_as_uint(v3.x); aI[k0][3] = __float_as_uint(v3.y);
    }

    float oR[2][2][2] = {}, oI[2][2][2] = {};
    float cR[2][4], cI[2][4];

    __syncthreads();

#pragma unroll 2
    for (int i = 0; i < 64; i++) {
        const int p = i & 1;
        if (i + 3 < 64) LOAD_SLICE(i + 3, (i + 3) & 3);
        asm volatile("cp.async.commit_group;");
        asm volatile("cp.async.wait_group 3;");
        __syncwarp();

        const float4* Bp = Bw + (i & 3) * SLICE_F4 + lane;
#pragma unroll
        for (int j = 0; j < 4; j++) { cR[p][j] = 0.f; cI[p][j] = 0.f; }
#pragma unroll
        for (int q = 0; q < 4; q++) {
            float4 bv = Bp[q * 32];
            unsigned b0 = __float_as_uint(bv.x), b1 = __float_as_uint(bv.y);
            unsigned b2 = __float_as_uint(bv.z), b3 = __float_as_uint(bv.w);
            MMA_TF32(cR[p], aR[2 * q],     b0, b1);
            MMA_TF32(cI[p], aI[2 * q],     b0, b1);
            MMA_TF32(cR[p], aR[2 * q + 1], b2, b3);
            MMA_TF32(cI[p], aI[2 * q + 1], b2, b3);
        }

        if (i > 0) {
            const int ip = i - 1, pp = p ^ 1;
#pragma unroll
            for (int rr = 0; rr < 2; rr++) {
                int flocal = g + rr * 8;
#pragma unroll
                for (int b = 0; b < 2; b++) {
                    float2 xv = Xs[(b * 64 + ip) * 16 + flocal];
#pragma unroll
                    for (int cc = 0; cc < 2; cc++) {
                        float kr = cR[pp][rr * 2 + cc];
                        float ki = cI[pp][rr * 2 + cc];
                        oR[b][rr][cc] += xv.x * kr - xv.y * ki;
                        oI[b][rr][cc] += xv.x * ki + xv.y * kr;
                    }
                }
            }
        }
    }
    {
        const int ip = 63, pp = 1;
#pragma unroll
        for (int rr = 0; rr < 2; rr++) {
            int flocal = g + rr * 8;
#pragma unroll
            for (int b = 0; b < 2; b++) {
                float2 xv = Xs[(b * 64 + ip) * 16 + flocal];
#pragma unroll
                for (int cc = 0; cc < 2; cc++) {
                    float kr = cR[pp][rr * 2 + cc];
                    float ki = cI[pp][rr * 2 + cc];
                    oR[b][rr][cc] += xv.x * kr - xv.y * ki;
                    oI[b][rr][cc] += xv.x * ki + xv.y * kr;
                }
            }
        }
    }

#pragma unroll
    for (int rr = 0; rr < 2; rr++) {
        int f = f0 + g + rr * 8;
        if (f < NBINS) {
#pragma unroll
            for (int b = 0; b < 2; b++)
#pragma unroll
                for (int cc = 0; cc < 2; cc++) {
                    int o = obase + tg * 2 + cc;
                    d_OutfP[kh][(b * 64 + o) * NBINS + f] =
                        make_float2(oR[b][rr][cc], oI[b][rr][cc]);
                }
        }
    }
}

// ---------------- inverse FFT: sums k-half partials, 2 rows per block ------
__global__ void fft_inv_kernel(float* __restrict__ out) {
    __shared__ float2 buf[NFFT];
    int t0 = 2 * blockIdx.x;
    const float2* P00 = d_OutfP[0] + (size_t)t0 * NBINS;
    const float2* P01 = d_OutfP[1] + (size_t)t0 * NBINS;
    const float2* P10 = d_OutfP[0] + (size_t)(t0 + 1) * NBINS;
    const float2* P11 = d_OutfP[1] + (size_t)(t0 + 1) * NBINS;
    for (int d = threadIdx.x; d < NFFT; d += 512) {
        int src = rev8(d);
        int s = (src <= 2048) ? src : (NFFT - src);
        float2 a = make_float2(P00[s].x + P01[s].x, P00[s].y + P01[s].y);
        float2 b = make_float2(P10[s].x + P11[s].x, P10[s].y + P11[s].y);
        float2 v;
        if (src <= 2048) v = make_float2(a.x - b.y, -a.y - b.x);
        else             v = make_float2(a.x + b.y,  a.y - b.x);
        buf[d] = v;
    }
    fft8_core(buf);
    const float inv = 1.0f / (float)NFFT;
    for (int n = threadIdx.x; n < LL; n += 512) {
        out[t0 * LL + n]       =  buf[n].x * inv;
        out[(t0 + 1) * LL + n] = -buf[n].y * inv;
    }
}

// ============================================================================
extern "C" void kernel_launch(void* const* d_in, const int* in_sizes, int n_in,
                              void* d_out, int out_size) {
    (void)in_sizes; (void)n_in; (void)out_size;
    const float* x  = (const float*)d_in[0];
    const float* W1 = (const float*)d_in[1];
    const float* W2 = (const float*)d_in[2];
    const float* W3 = (const float*)d_in[3];
    float* out = (float*)d_out;

    cudaFuncSetAttribute(k45_kernel,
                         cudaFuncAttributeMaxDynamicSharedMemorySize, K45_SMEM);

    setup_h2_kernel<<<2048, 256>>>(W1, W2, W3);
    fft_gx_kernel<<<128, 512>>>(x);
    k45_kernel<<<dim3(129, 2), 256, K45_SMEM>>>();
    fft_inv_kernel<<<64, 512>>>(out);
}

// round 12
// speedup vs baseline: 1.3493x; 1.0426x over previous
#include <cuda_runtime.h>
#include <math.h>

// ============================================================================
// CKConv via FFT convolution, fused tf32 tensor-core spectrum GEMM.
//   Outf[b,o,f] = Σ_i Xf[b,i,f] · Σ_m Gf[m,f]·W3[m,o*64+i]    (Kf never stored)
// Radix-8 FFTs (4 stages), COALESCED gmem loads (linear read, smem scatter
// through the involutive digit-reversal). k45 frozen from R10.
// ============================================================================

#define LL     2048
#define NFFT   4096
#define HID    128
#define NBINS  2049   // NFFT/2 + 1

__device__ float  d_h2T[HID * LL];          // [m][l]
__device__ float4 d_W3f4[64 * 8 * 8 * 32];  // [i][warp][kc2][lane] frag quads
__device__ float2 d_tw4[NFFT];
__device__ float2 d_Gf[HID * NFFT];         // [m][f] tf32-rounded, mirrored
__device__ float2 d_Xf[128 * NFFT];         // [b*64+i][f], mirrored
__device__ float2 d_OutfP[2][128 * NBINS];  // per-k-half partials

__device__ __forceinline__ float to_tf32(float x) {
    unsigned u;
    asm("cvt.rna.tf32.f32 %0, %1;" : "=r"(u) : "f"(x));
    return __uint_as_float(u);
}

// -------------- fused: SIREN h2 + twiddles + W3 fragment repack ------------
__global__ void setup_h2_kernel(const float* __restrict__ W1,
                                const float* __restrict__ W2,
                                const float* __restrict__ W3) {
    __shared__ float h1[HID];
    const int tid = threadIdx.x;
    const int l   = blockIdx.x;     // 0..2047

    if (tid < HID) {
        float rel = -1.0f + 2.0f * (float)l / 2047.0f;
        h1[tid] = sinf(30.0f * rel * W1[tid]);
    }
    __syncthreads();
    if (tid < HID) {
        float acc = 0.0f;
#pragma unroll 16
        for (int m = 0; m < HID; m++)
            acc += h1[m] * W2[m * HID + tid];
        d_h2T[tid * LL + l] = sinf(30.0f * acc);
    } else if (tid < HID + 64) {
        int idx = blockIdx.x * 64 + (tid - HID);   // 0..131071
        if (idx < NFFT) {
            double a = 2.0 * 3.14159265358979323846 * (double)idx / (double)NFFT;
            d_tw4[idx] = make_float2((float)cos(a), (float)(-sin(a)));
        }
        int lane = idx & 31;
        int kc2  = (idx >> 5) & 7;
        int w    = (idx >> 8) & 7;
        int i    = idx >> 11;
        int tg = lane & 3, g = lane >> 2;
        int col = (w * 8 + g) * 64 + i;
        int mA  = (2 * kc2) * 8 + tg;
        int mB  = (2 * kc2 + 1) * 8 + tg;
        d_W3f4[idx] = make_float4(to_tf32(W3[mA * 4096 + col]),
                                  to_tf32(W3[(mA + 4) * 4096 + col]),
                                  to_tf32(W3[mB * 4096 + col]),
                                  to_tf32(W3[(mB + 4) * 4096 + col]));
    }
}

// ------------------------------------------------------- radix-8 FFT core --
__device__ __forceinline__ int rev8(int d) {   // reverse 4 octal digits (involution)
    return ((d & 7) << 9) | (((d >> 3) & 7) << 6) |
           (((d >> 6) & 7) << 3) | ((d >> 9) & 7);
}
__device__ __forceinline__ float2 cmul(float2 a, float2 b) {
    return make_float2(a.x * b.x - a.y * b.y, a.x * b.y + a.y * b.x);
}

#define SQRT1_2 0.70710678118654752f

// 4 stages, 512 threads, one radix-8 butterfly per thread per stage.
__device__ __forceinline__ void fft8_core(float2* buf) {
#pragma unroll
    for (int st = 0; st < 4; st++) {
        const int q = 1 << (3 * st);
        const int tstep = NFFT >> (3 * st + 3);
        __syncthreads();
        const int bf = threadIdx.x;                // 0..511
        const int j  = bf & (q - 1);
        const int base = ((bf >> (3 * st)) << (3 * st + 3)) + j;

        float2 u[8];
        u[0] = buf[base];
#pragma unroll
        for (int t = 1; t < 8; t++) {
            float2 v = buf[base + t * q];
            u[t] = (st == 0) ? v : cmul(v, d_tw4[j * t * tstep]);
        }
        float2 ea = make_float2(u[0].x + u[4].x, u[0].y + u[4].y);
        float2 eb = make_float2(u[0].x - u[4].x, u[0].y - u[4].y);
        float2 ec = make_float2(u[2].x + u[6].x, u[2].y + u[6].y);
        float2 ed = make_float2(u[2].x - u[6].x, u[2].y - u[6].y);
        float2 E0 = make_float2(ea.x + ec.x, ea.y + ec.y);
        float2 E1 = make_float2(eb.x + ed.y, eb.y - ed.x);
        float2 E2 = make_float2(ea.x - ec.x, ea.y - ec.y);
        float2 E3 = make_float2(eb.x - ed.y, eb.y + ed.x);
        float2 oa = make_float2(u[1].x + u[5].x, u[1].y + u[5].y);
        float2 ob = make_float2(u[1].x - u[5].x, u[1].y - u[5].y);
        float2 oc = make_float2(u[3].x + u[7].x, u[3].y + u[7].y);
        float2 od = make_float2(u[3].x - u[7].x, u[3].y - u[7].y);
        float2 O0 = make_float2(oa.x + oc.x, oa.y + oc.y);
        float2 O1 = make_float2(ob.x + od.y, ob.y - od.x);
        float2 O2 = make_float2(oa.x - oc.x, oa.y - oc.y);
        float2 O3 = make_float2(ob.x - od.y, ob.y + od.x);
        float2 T1 = make_float2(SQRT1_2 * (O1.x + O1.y), SQRT1_2 * (O1.y - O1.x));
        float2 T2 = make_float2(O2.y, -O2.x);
        float2 T3 = make_float2(SQRT1_2 * (O3.y - O3.x), -SQRT1_2 * (O3.x + O3.y));
        buf[base]         = make_float2(E0.x + O0.x, E0.y + O0.y);
        buf[base + 4 * q] = make_float2(E0.x - O0.x, E0.y - O0.y);
        buf[base + 1 * q] = make_float2(E1.x + T1.x, E1.y + T1.y);
        buf[base + 5 * q] = make_float2(E1.x - T1.x, E1.y - T1.y);
        buf[base + 2 * q] = make_float2(E2.x + T2.x, E2.y + T2.y);
        buf[base + 6 * q] = make_float2(E2.x - T2.x, E2.y - T2.y);
        buf[base + 3 * q] = make_float2(E3.x + T3.x, E3.y + T3.y);
        buf[base + 7 * q] = make_float2(E3.x - T3.x, E3.y - T3.y);
    }
    __syncthreads();
}

// ---------------------------- forward FFTs, two real rows packed per block --
// COALESCED: read gmem linearly in s, scatter buf[rev8(s)] (rev8 involutive).
__global__ void fft_gx_kernel(const float* __restrict__ x) {
    __shared__ float2 buf[NFFT];
    int blk = blockIdx.x;
    bool isg = blk < 64;
    int r0 = isg ? 2 * blk : 2 * (blk - 64);
    for (int s = threadIdx.x; s < NFFT; s += 512) {
        float va = 0.0f, vb = 0.0f;
        if (s < LL) {
            if (isg) {
                va = d_h2T[r0 * LL + (LL - 1 - s)];        // reverse-linear: coalesced
                vb = d_h2T[(r0 + 1) * LL + (LL - 1 - s)];
            } else {
                va = x[r0 * LL + s];
                vb = x[(r0 + 1) * LL + s];
            }
        }
        buf[rev8(s)] = make_float2(va, vb);
    }
    fft8_core(buf);
    for (int f = threadIdx.x; f <= 2048; f += 512) {
        float2 Zf = buf[f];
        float2 Zc = buf[(NFFT - f) & (NFFT - 1)];
        float2 A = make_float2((Zf.x + Zc.x) * 0.5f, (Zf.y - Zc.y) * 0.5f);
        float2 B = make_float2((Zf.y + Zc.y) * 0.5f, (Zc.x - Zf.x) * 0.5f);
        if (isg) {
            A = make_float2(to_tf32(A.x), to_tf32(A.y));
            B = make_float2(to_tf32(B.x), to_tf32(B.y));
            d_Gf[r0 * NFFT + f]       = A;
            d_Gf[(r0 + 1) * NFFT + f] = B;
            if (f > 0 && f < 2048) {
                d_Gf[r0 * NFFT + NFFT - f]       = make_float2(A.x, -A.y);
                d_Gf[(r0 + 1) * NFFT + NFFT - f] = make_float2(B.x, -B.y);
            }
        } else {
            d_Xf[r0 * NFFT + f]       = A;
            d_Xf[(r0 + 1) * NFFT + f] = B;
            if (f > 0 && f < 2048) {
                d_Xf[r0 * NFFT + NFFT - f]       = make_float2(A.x, -A.y);
                d_Xf[(r0 + 1) * NFFT + NFFT - f] = make_float2(B.x, -B.y);
            }
        }
    }
}

// ----------------------- k45: fused kernel-spectrum GEMM + per-bin mixing --
// (frozen from R10: 41.6 us)
#define MMA_TF32(C, A, B0, B1)                                              \
    asm volatile("mma.sync.aligned.m16n8k8.row.col.f32.tf32.tf32.f32 "      \
        "{%0,%1,%2,%3}, {%4,%5,%6,%7}, {%8,%9}, {%0,%1,%2,%3};"             \
        : "+f"(C[0]), "+f"(C[1]), "+f"(C[2]), "+f"(C[3])                    \
        : "r"(A[0]), "r"(A[1]), "r"(A[2]), "r"(A[3]), "r"(B0), "r"(B1))

#define CP16(dst_u32, src_ptr)                                              \
    asm volatile("cp.async.cg.shared.global [%0], [%1], 16;"                \
                 :: "r"(dst_u32), "l"(src_ptr))

#define XS_FLOATS   (128 * 16 * 2)
#define SLICE_F4    128
#define K45_SMEM    (XS_FLOATS * 4 + 8 * 4 * SLICE_F4 * 16)

__global__ void __launch_bounds__(256, 2) k45_kernel() {
    extern __shared__ float smem[];
    float2* Xs = (float2*)smem;

    const int f0   = blockIdx.x * 16;
    const int kh   = blockIdx.y;
    const int kofs = kh * 64;
    const int tid  = threadIdx.x;
    const int lane = tid & 31;
    const int warp = tid >> 5;
    const int g    = lane >> 2;
    const int tg   = lane & 3;
    const int obase = warp * 8;

    float4* Bw = (float4*)(smem + XS_FLOATS) + warp * (4 * SLICE_F4);
    unsigned bw_base = (unsigned)__cvta_generic_to_shared(Bw);

#define LOAD_SLICE(i_, buf_)                                                \
    {                                                                       \
        const float4* srcb = d_W3f4 + (((i_) * 8 + warp) * 8 + kh * 4) * 32;\
        unsigned dstb = bw_base + (buf_) * (SLICE_F4 * 16);                 \
        _Pragma("unroll")                                                   \
        for (int j = 0; j < 4; j++)                                         \
            CP16(dstb + (lane + (j << 5)) * 16, srcb + lane + (j << 5));    \
    }

    LOAD_SLICE(0, 0); asm volatile("cp.async.commit_group;");
    LOAD_SLICE(1, 1); asm volatile("cp.async.commit_group;");
    LOAD_SLICE(2, 2); asm volatile("cp.async.commit_group;");

    for (int idx = tid; idx < 128 * 16; idx += 256) {
        int row = idx >> 4, ff = idx & 15;
        Xs[idx] = d_Xf[row * NFFT + f0 + ff];
    }

    unsigned aR[8][4], aI[8][4];
#pragma unroll
    for (int k0 = 0; k0 < 8; k0++) {
        int kk = kofs + k0 * 8;
        float2 v0 = d_Gf[(kk + tg)     * NFFT + f0 + g];
        float2 v1 = d_Gf[(kk + tg)     * NFFT + f0 + g + 8];
        float2 v2 = d_Gf[(kk + tg + 4) * NFFT + f0 + g];
        float2 v3 = d_Gf[(kk + tg + 4) * NFFT + f0 + g + 8];
        aR[k0][0] = __float_as_uint(v0.x); aI[k0][0] = __float_as_uint(v0.y);
        aR[k0][1] = __float_as_uint(v1.x); aI[k0][1] = __float_as_uint(v1.y);
        aR[k0][2] = __float_as_uint(v2.x); aI[k0][2] = __float_as_uint(v2.y);
        aR[k0][3] = __float_as_uint(v3.x); aI[k0][3] = __float_as_uint(v3.y);
    }

    float oR[2][2][2] = {}, oI[2][2][2] = {};
    float cR[2][4], cI[2][4];

    __syncthreads();

#pragma unroll 2
    for (int i = 0; i < 64; i++) {
        const int p = i & 1;
        if (i + 3 < 64) LOAD_SLICE(i + 3, (i + 3) & 3);
        asm volatile("cp.async.commit_group;");
        asm volatile("cp.async.wait_group 3;");
        __syncwarp();

        const float4* Bp = Bw + (i & 3) * SLICE_F4 + lane;
#pragma unroll
        for (int j = 0; j < 4; j++) { cR[p][j] = 0.f; cI[p][j] = 0.f; }
#pragma unroll
        for (int q = 0; q < 4; q++) {
            float4 bv = Bp[q * 32];
            unsigned b0 = __float_as_uint(bv.x), b1 = __float_as_uint(bv.y);
            unsigned b2 = __float_as_uint(bv.z), b3 = __float_as_uint(bv.w);
            MMA_TF32(cR[p], aR[2 * q],     b0, b1);
            MMA_TF32(cI[p], aI[2 * q],     b0, b1);
            MMA_TF32(cR[p], aR[2 * q + 1], b2, b3);
            MMA_TF32(cI[p], aI[2 * q + 1], b2, b3);
        }

        if (i > 0) {
            const int ip = i - 1, pp = p ^ 1;
#pragma unroll
            for (int rr = 0; rr < 2; rr++) {
                int flocal = g + rr * 8;
#pragma unroll
                for (int b = 0; b < 2; b++) {
                    float2 xv = Xs[(b * 64 + ip) * 16 + flocal];
#pragma unroll
                    for (int cc = 0; cc < 2; cc++) {
                        float kr = cR[pp][rr * 2 + cc];
                        float ki = cI[pp][rr * 2 + cc];
                        oR[b][rr][cc] += xv.x * kr - xv.y * ki;
                        oI[b][rr][cc] += xv.x * ki + xv.y * kr;
                    }
                }
            }
        }
    }
    {
        const int ip = 63, pp = 1;
#pragma unroll
        for (int rr = 0; rr < 2; rr++) {
            int flocal = g + rr * 8;
#pragma unroll
            for (int b = 0; b < 2; b++) {
                float2 xv = Xs[(b * 64 + ip) * 16 + flocal];
#pragma unroll
                for (int cc = 0; cc < 2; cc++) {
                    float kr = cR[pp][rr * 2 + cc];
                    float ki = cI[pp][rr * 2 + cc];
                    oR[b][rr][cc] += xv.x * kr - xv.y * ki;
                    oI[b][rr][cc] += xv.x * ki + xv.y * kr;
                }
            }
        }
    }

#pragma unroll
    for (int rr = 0; rr < 2; rr++) {
        int f = f0 + g + rr * 8;
        if (f < NBINS) {
#pragma unroll
            for (int b = 0; b < 2; b++)
#pragma unroll
                for (int cc = 0; cc < 2; cc++) {
                    int o = obase + tg * 2 + cc;
                    d_OutfP[kh][(b * 64 + o) * NBINS + f] =
                        make_float2(oR[b][rr][cc], oI[b][rr][cc]);
                }
        }
    }
}

// ---------------- inverse FFT: sums k-half partials, 2 rows per block ------
// COALESCED: read partials linearly in s, scatter buf[rev8(s)].
__global__ void fft_inv_kernel(float* __restrict__ out) {
    __shared__ float2 buf[NFFT];
    int t0 = 2 * blockIdx.x;
    const float2* P00 = d_OutfP[0] + (size_t)t0 * NBINS;
    const float2* P01 = d_OutfP[1] + (size_t)t0 * NBINS;
    const float2* P10 = d_OutfP[0] + (size_t)(t0 + 1) * NBINS;
    const float2* P11 = d_OutfP[1] + (size_t)(t0 + 1) * NBINS;
    for (int s = threadIdx.x; s < NFFT; s += 512) {
        int sb = (s <= 2048) ? s : (NFFT - s);
        float2 a = make_float2(P00[sb].x + P01[sb].x, P00[sb].y + P01[sb].y);
        float2 b = make_float2(P10[sb].x + P11[sb].x, P10[sb].y + P11[sb].y);
        float2 v;
        if (s <= 2048) v = make_float2(a.x - b.y, -a.y - b.x);
        else           v = make_float2(a.x + b.y,  a.y - b.x);
        buf[rev8(s)] = v;
    }
    fft8_core(buf);
    const float inv = 1.0f / (float)NFFT;
    for (int n = threadIdx.x; n < LL; n += 512) {
        out[t0 * LL + n]       =  buf[n].x * inv;
        out[(t0 + 1) * LL + n] = -buf[n].y * inv;
    }
}

// ============================================================================
extern "C" void kernel_launch(void* const* d_in, const int* in_sizes, int n_in,
                              void* d_out, int out_size) {
    (void)in_sizes; (void)n_in; (void)out_size;
    const float* x  = (const float*)d_in[0];
    const float* W1 = (const float*)d_in[1];
    const float* W2 = (const float*)d_in[2];
    const float* W3 = (const float*)d_in[3];
    float* out = (float*)d_out;

    cudaFuncSetAttribute(k45_kernel,
                         cudaFuncAttributeMaxDynamicSharedMemorySize, K45_SMEM);

    setup_h2_kernel<<<2048, 256>>>(W1, W2, W3);
    fft_gx_kernel<<<128, 512>>>(x);
    k45_kernel<<<dim3(129, 2), 256, K45_SMEM>>>();
    fft_inv_kernel<<<64, 512>>>(out);
}

// round 13
// speedup vs baseline: 1.4107x; 1.0455x over previous
#include <cuda_runtime.h>
#include <math.h>

// ============================================================================
// CKConv via FFT convolution, fused tf32 tensor-core spectrum GEMM.
//   Outf[b,o,f] = Σ_i Xf[b,i,f] · Σ_m Gf[m,f]·W3[m,o*64+i]    (Kf never stored)
// Forward: radix-8 4096 FFTs (2 real rows packed). Inverse: per-row N/2 trick,
// 2048-pt mixed-radix [4,8,8,8] FFT, grid 128. k45 frozen from R10.
// ============================================================================

#define LL     2048
#define NFFT   4096
#define HID    128
#define NBINS  2049   // NFFT/2 + 1

__device__ float  d_h2T[HID * LL];          // [m][l]
__device__ float4 d_W3f4[64 * 8 * 8 * 32];  // [i][warp][kc2][lane] frag quads
__device__ float2 d_tw4[NFFT];
__device__ float2 d_Gf[HID * NFFT];         // [m][f] tf32-rounded, mirrored
__device__ float2 d_Xf[128 * NFFT];         // [b*64+i][f], mirrored
__device__ float2 d_OutfP[2][128 * NBINS];  // per-k-half partials

__device__ __forceinline__ float to_tf32(float x) {
    unsigned u;
    asm("cvt.rna.tf32.f32 %0, %1;" : "=r"(u) : "f"(x));
    return __uint_as_float(u);
}

// -------------- fused: SIREN h2 + twiddles + W3 fragment repack ------------
__global__ void setup_h2_kernel(const float* __restrict__ W1,
                                const float* __restrict__ W2,
                                const float* __restrict__ W3) {
    __shared__ float h1[HID];
    const int tid = threadIdx.x;
    const int l   = blockIdx.x;     // 0..2047

    if (tid < HID) {
        float rel = -1.0f + 2.0f * (float)l / 2047.0f;
        h1[tid] = sinf(30.0f * rel * W1[tid]);
    }
    __syncthreads();
    if (tid < HID) {
        float acc = 0.0f;
#pragma unroll 16
        for (int m = 0; m < HID; m++)
            acc += h1[m] * W2[m * HID + tid];
        d_h2T[tid * LL + l] = sinf(30.0f * acc);
    } else if (tid < HID + 64) {
        int idx = blockIdx.x * 64 + (tid - HID);   // 0..131071
        if (idx < NFFT) {
            double a = 2.0 * 3.14159265358979323846 * (double)idx / (double)NFFT;
            d_tw4[idx] = make_float2((float)cos(a), (float)(-sin(a)));
        }
        int lane = idx & 31;
        int kc2  = (idx >> 5) & 7;
        int w    = (idx >> 8) & 7;
        int i    = idx >> 11;
        int tg = lane & 3, g = lane >> 2;
        int col = (w * 8 + g) * 64 + i;
        int mA  = (2 * kc2) * 8 + tg;
        int mB  = (2 * kc2 + 1) * 8 + tg;
        d_W3f4[idx] = make_float4(to_tf32(W3[mA * 4096 + col]),
                                  to_tf32(W3[(mA + 4) * 4096 + col]),
                                  to_tf32(W3[mB * 4096 + col]),
                                  to_tf32(W3[(mB + 4) * 4096 + col]));
    }
}

// ------------------------------------------------------------- FFT helpers --
__device__ __forceinline__ int rev8(int d) {   // reverse 4 octal digits
    return ((d & 7) << 9) | (((d >> 3) & 7) << 6) |
           (((d >> 6) & 7) << 3) | ((d >> 9) & 7);
}
__device__ __forceinline__ float2 cmul(float2 a, float2 b) {
    return make_float2(a.x * b.x - a.y * b.y, a.x * b.y + a.y * b.x);
}
#define SQRT1_2 0.70710678118654752f

// radix-8 butterfly: u[0..7] in, results in place (order v0..v7)
__device__ __forceinline__ void bfly8(float2* u) {
    float2 ea = make_float2(u[0].x + u[4].x, u[0].y + u[4].y);
    float2 eb = make_float2(u[0].x - u[4].x, u[0].y - u[4].y);
    float2 ec = make_float2(u[2].x + u[6].x, u[2].y + u[6].y);
    float2 ed = make_float2(u[2].x - u[6].x, u[2].y - u[6].y);
    float2 E0 = make_float2(ea.x + ec.x, ea.y + ec.y);
    float2 E1 = make_float2(eb.x + ed.y, eb.y - ed.x);
    float2 E2 = make_float2(ea.x - ec.x, ea.y - ec.y);
    float2 E3 = make_float2(eb.x - ed.y, eb.y + ed.x);
    float2 oa = make_float2(u[1].x + u[5].x, u[1].y + u[5].y);
    float2 ob = make_float2(u[1].x - u[5].x, u[1].y - u[5].y);
    float2 oc = make_float2(u[3].x + u[7].x, u[3].y + u[7].y);
    float2 od = make_float2(u[3].x - u[7].x, u[3].y - u[7].y);
    float2 O0 = make_float2(oa.x + oc.x, oa.y + oc.y);
    float2 O1 = make_float2(ob.x + od.y, ob.y - od.x);
    float2 O2 = make_float2(oa.x - oc.x, oa.y - oc.y);
    float2 O3 = make_float2(ob.x - od.y, ob.y + od.x);
    float2 T1 = make_float2(SQRT1_2 * (O1.x + O1.y), SQRT1_2 * (O1.y - O1.x));
    float2 T2 = make_float2(O2.y, -O2.x);
    float2 T3 = make_float2(SQRT1_2 * (O3.y - O3.x), -SQRT1_2 * (O3.x + O3.y));
    u[0] = make_float2(E0.x + O0.x, E0.y + O0.y);
    u[4] = make_float2(E0.x - O0.x, E0.y - O0.y);
    u[1] = make_float2(E1.x + T1.x, E1.y + T1.y);
    u[5] = make_float2(E1.x - T1.x, E1.y - T1.y);
    u[2] = make_float2(E2.x + T2.x, E2.y + T2.y);
    u[6] = make_float2(E2.x - T2.x, E2.y - T2.y);
    u[3] = make_float2(E3.x + T3.x, E3.y + T3.y);
    u[7] = make_float2(E3.x - T3.x, E3.y - T3.y);
}

// ------------------- 4096-pt radix-8 core (512 threads, 4 stages) ----------
__device__ __forceinline__ void fft8_core(float2* buf) {
    const int tid = threadIdx.x;
    // stage 0 (q=1): consecutive 8, vectorized float4, no twiddles
    __syncthreads();
    {
        float4* b4 = (float4*)(buf + tid * 8);
        float2 u[8];
#pragma unroll
        for (int h = 0; h < 4; h++) {
            float4 v = b4[h];
            u[2 * h]     = make_float2(v.x, v.y);
            u[2 * h + 1] = make_float2(v.z, v.w);
        }
        bfly8(u);
#pragma unroll
        for (int h = 0; h < 4; h++)
            b4[h] = make_float4(u[2 * h].x, u[2 * h].y,
                                u[2 * h + 1].x, u[2 * h + 1].y);
    }
#pragma unroll
    for (int st = 1; st < 4; st++) {
        const int q = 1 << (3 * st);
        const int tstep = NFFT >> (3 * st + 3);
        __syncthreads();
        const int j = tid & (q - 1);
        const int base = ((tid >> (3 * st)) << (3 * st + 3)) + j;
        float2 u[8];
        u[0] = buf[base];
#pragma unroll
        for (int t = 1; t < 8; t++)
            u[t] = cmul(buf[base + t * q], d_tw4[j * t * tstep]);
        bfly8(u);
#pragma unroll
        for (int t = 0; t < 8; t++)
            buf[base + t * q] = u[t];
    }
    __syncthreads();
}

// --------------- 2048-pt mixed-radix [4,8,8,8] core (256 threads) ----------
// input scattered via addr2048(); natural-order output.
__device__ __forceinline__ int addr2048(int s) {
    return (s >> 9) + 4 * ((s >> 6) & 7) + 32 * ((s >> 3) & 7) + 256 * (s & 7);
}
__device__ __forceinline__ void fft2048_core(float2* buf) {
    const int tid = threadIdx.x;    // 0..255
    // stage 0: radix-4, q=1, two butterflies/thread, float4 vectorized
    __syncthreads();
#pragma unroll
    for (int k = 0; k < 2; k++) {
        float4* b4 = (float4*)(buf + ((tid + (k << 8)) << 2));
        float4 lo = b4[0], hi = b4[1];
        float2 u0 = make_float2(lo.x, lo.y), u1 = make_float2(lo.z, lo.w);
        float2 u2 = make_float2(hi.x, hi.y), u3 = make_float2(hi.z, hi.w);
        float2 a = make_float2(u0.x + u2.x, u0.y + u2.y);
        float2 b = make_float2(u0.x - u2.x, u0.y - u2.y);
        float2 c = make_float2(u1.x + u3.x, u1.y + u3.y);
        float2 d = make_float2(u1.x - u3.x, u1.y - u3.y);
        b4[0] = make_float4(a.x + c.x, a.y + c.y, b.x + d.y, b.y - d.x);
        b4[1] = make_float4(a.x - c.x, a.y - c.y, b.x - d.y, b.y + d.x);
    }
    // radix-8 stages: q = 4, 32, 256 ; tw4 step = 128, 16, 2
#pragma unroll
    for (int st = 0; st < 3; st++) {
        const int q = 4 << (3 * st);
        const int tstep = 128 >> (3 * st);
        const int sh = 2 + 3 * st;
        __syncthreads();
        const int j = tid & (q - 1);
        const int base = ((tid >> sh) << (sh + 3)) + j;
        float2 u[8];
        u[0] = buf[base];
#pragma unroll
        for (int t = 1; t < 8; t++)
            u[t] = cmul(buf[base + t * q], d_tw4[j * t * tstep]);
        bfly8(u);
#pragma unroll
        for (int t = 0; t < 8; t++)
            buf[base + t * q] = u[t];
    }
    __syncthreads();
}

// ---------------------------- forward FFTs, two real rows packed per block --
__global__ void fft_gx_kernel(const float* __restrict__ x) {
    __shared__ float2 buf[NFFT];
    int blk = blockIdx.x;
    bool isg = blk < 64;
    int r0 = isg ? 2 * blk : 2 * (blk - 64);
    for (int s = threadIdx.x; s < NFFT; s += 512) {
        float va = 0.0f, vb = 0.0f;
        if (s < LL) {
            if (isg) {
                va = d_h2T[r0 * LL + (LL - 1 - s)];
                vb = d_h2T[(r0 + 1) * LL + (LL - 1 - s)];
            } else {
                va = x[r0 * LL + s];
                vb = x[(r0 + 1) * LL + s];
            }
        }
        buf[rev8(s)] = make_float2(va, vb);
    }
    fft8_core(buf);
    for (int f = threadIdx.x; f <= 2048; f += 512) {
        float2 Zf = buf[f];
        float2 Zc = buf[(NFFT - f) & (NFFT - 1)];
        float2 A = make_float2((Zf.x + Zc.x) * 0.5f, (Zf.y - Zc.y) * 0.5f);
        float2 B = make_float2((Zf.y + Zc.y) * 0.5f, (Zc.x - Zf.x) * 0.5f);
        if (isg) {
            A = make_float2(to_tf32(A.x), to_tf32(A.y));
            B = make_float2(to_tf32(B.x), to_tf32(B.y));
            d_Gf[r0 * NFFT + f]       = A;
            d_Gf[(r0 + 1) * NFFT + f] = B;
            if (f > 0 && f < 2048) {
                d_Gf[r0 * NFFT + NFFT - f]       = make_float2(A.x, -A.y);
                d_Gf[(r0 + 1) * NFFT + NFFT - f] = make_float2(B.x, -B.y);
            }
        } else {
            d_Xf[r0 * NFFT + f]       = A;
            d_Xf[(r0 + 1) * NFFT + f] = B;
            if (f > 0 && f < 2048) {
                d_Xf[r0 * NFFT + NFFT - f]       = make_float2(A.x, -A.y);
                d_Xf[(r0 + 1) * NFFT + NFFT - f] = make_float2(B.x, -B.y);
            }
        }
    }
}

// ----------------------- k45: fused kernel-spectrum GEMM + per-bin mixing --
// (frozen from R10: 41.6 us)
#define MMA_TF32(C, A, B0, B1)                                              \
    asm volatile("mma.sync.aligned.m16n8k8.row.col.f32.tf32.tf32.f32 "      \
        "{%0,%1,%2,%3}, {%4,%5,%6,%7}, {%8,%9}, {%0,%1,%2,%3};"             \
        : "+f"(C[0]), "+f"(C[1]), "+f"(C[2]), "+f"(C[3])                    \
        : "r"(A[0]), "r"(A[1]), "r"(A[2]), "r"(A[3]), "r"(B0), "r"(B1))

#define CP16(dst_u32, src_ptr)                                              \
    asm volatile("cp.async.cg.shared.global [%0], [%1], 16;"                \
                 :: "r"(dst_u32), "l"(src_ptr))

#define XS_FLOATS   (128 * 16 * 2)
#define SLICE_F4    128
#define K45_SMEM    (XS_FLOATS * 4 + 8 * 4 * SLICE_F4 * 16)

__global__ void __launch_bounds__(256, 2) k45_kernel() {
    extern __shared__ float smem[];
    float2* Xs = (float2*)smem;

    const int f0   = blockIdx.x * 16;
    const int kh   = blockIdx.y;
    const int kofs = kh * 64;
    const int tid  = threadIdx.x;
    const int lane = tid & 31;
    const int warp = tid >> 5;
    const int g    = lane >> 2;
    const int tg   = lane & 3;
    const int obase = warp * 8;

    float4* Bw = (float4*)(smem + XS_FLOATS) + warp * (4 * SLICE_F4);
    unsigned bw_base = (unsigned)__cvta_generic_to_shared(Bw);

#define LOAD_SLICE(i_, buf_)                                                \
    {                                                                       \
        const float4* srcb = d_W3f4 + (((i_) * 8 + warp) * 8 + kh * 4) * 32;\
        unsigned dstb = bw_base + (buf_) * (SLICE_F4 * 16);                 \
        _Pragma("unroll")                                                   \
        for (int j = 0; j < 4; j++)                                         \
            CP16(dstb + (lane + (j << 5)) * 16, srcb + lane + (j << 5));    \
    }

    LOAD_SLICE(0, 0); asm volatile("cp.async.commit_group;");
    LOAD_SLICE(1, 1); asm volatile("cp.async.commit_group;");
    LOAD_SLICE(2, 2); asm volatile("cp.async.commit_group;");

    for (int idx = tid; idx < 128 * 16; idx += 256) {
        int row = idx >> 4, ff = idx & 15;
        Xs[idx] = d_Xf[row * NFFT + f0 + ff];
    }

    unsigned aR[8][4], aI[8][4];
#pragma unroll
    for (int k0 = 0; k0 < 8; k0++) {
        int kk = kofs + k0 * 8;
        float2 v0 = d_Gf[(kk + tg)     * NFFT + f0 + g];
        float2 v1 = d_Gf[(kk + tg)     * NFFT + f0 + g + 8];
        float2 v2 = d_Gf[(kk + tg + 4) * NFFT + f0 + g];
        float2 v3 = d_Gf[(kk + tg + 4) * NFFT + f0 + g + 8];
        aR[k0][0] = __float_as_uint(v0.x); aI[k0][0] = __float_as_uint(v0.y);
        aR[k0][1] = __float_as_uint(v1.x); aI[k0][1] = __float_as_uint(v1.y);
        aR[k0][2] = __float_as_uint(v2.x); aI[k0][2] = __float_as_uint(v2.y);
        aR[k0][3] = __float_as_uint(v3.x); aI[k0][3] = __float_as_uint(v3.y);
    }

    float oR[2][2][2] = {}, oI[2][2][2] = {};
    float cR[2][4], cI[2][4];

    __syncthreads();

#pragma unroll 2
    for (int i = 0; i < 64; i++) {
        const int p = i & 1;
        if (i + 3 < 64) LOAD_SLICE(i + 3, (i + 3) & 3);
        asm volatile("cp.async.commit_group;");
        asm volatile("cp.async.wait_group 3;");
        __syncwarp();

        const float4* Bp = Bw + (i & 3) * SLICE_F4 + lane;
#pragma unroll
        for (int j = 0; j < 4; j++) { cR[p][j] = 0.f; cI[p][j] = 0.f; }
#pragma unroll
        for (int q = 0; q < 4; q++) {
            float4 bv = Bp[q * 32];
            unsigned b0 = __float_as_uint(bv.x), b1 = __float_as_uint(bv.y);
            unsigned b2 = __float_as_uint(bv.z), b3 = __float_as_uint(bv.w);
            MMA_TF32(cR[p], aR[2 * q],     b0, b1);
            MMA_TF32(cI[p], aI[2 * q],     b0, b1);
            MMA_TF32(cR[p], aR[2 * q + 1], b2, b3);
            MMA_TF32(cI[p], aI[2 * q + 1], b2, b3);
        }

        if (i > 0) {
            const int ip = i - 1, pp = p ^ 1;
#pragma unroll
            for (int rr = 0; rr < 2; rr++) {
                int flocal = g + rr * 8;
#pragma unroll
                for (int b = 0; b < 2; b++) {
                    float2 xv = Xs[(b * 64 + ip) * 16 + flocal];
#pragma unroll
                    for (int cc = 0; cc < 2; cc++) {
                        float kr = cR[pp][rr * 2 + cc];
                        float ki = cI[pp][rr * 2 + cc];
                        oR[b][rr][cc] += xv.x * kr - xv.y * ki;
                        oI[b][rr][cc] += xv.x * ki + xv.y * kr;
                    }
                }
            }
        }
    }
    {
        const int ip = 63, pp = 1;
#pragma unroll
        for (int rr = 0; rr < 2; rr++) {
            int flocal = g + rr * 8;
#pragma unroll
            for (int b = 0; b < 2; b++) {
                float2 xv = Xs[(b * 64 + ip) * 16 + flocal];
#pragma unroll
                for (int cc = 0; cc < 2; cc++) {
                    float kr = cR[pp][rr * 2 + cc];
                    float ki = cI[pp][rr * 2 + cc];
                    oR[b][rr][cc] += xv.x * kr - xv.y * ki;
                    oI[b][rr][cc] += xv.x * ki + xv.y * kr;
                }
            }
        }
    }

#pragma unroll
    for (int rr = 0; rr < 2; rr++) {
        int f = f0 + g + rr * 8;
        if (f < NBINS) {
#pragma unroll
            for (int b = 0; b < 2; b++)
#pragma unroll
                for (int cc = 0; cc < 2; cc++) {
                    int o = obase + tg * 2 + cc;
                    d_OutfP[kh][(b * 64 + o) * NBINS + f] =
                        make_float2(oR[b][rr][cc], oI[b][rr][cc]);
                }
        }
    }
}

// ---------------- inverse FFT: ONE row per block, N/2 real-IFFT trick ------
// Z[f] = A + iB; A=(Y[f]+conj(Y[2048-f]))/2; B=(Y[f]-conj(Y[2048-f]))/2*conj(tw4[f])
// z = IFFT_2048(Z) via conj(FFT(conj Z))/2048;  y[2k],y[2k+1] = Re,Im z[k].
__global__ void fft_inv_kernel(float* __restrict__ out) {
    __shared__ float2 buf[2048];
    int r = blockIdx.x;   // 0..127
    const float2* P0 = d_OutfP[0] + (size_t)r * NBINS;
    const float2* P1 = d_OutfP[1] + (size_t)r * NBINS;
    for (int s = threadIdx.x; s < 2048; s += 256) {
        int ms = 2048 - s;
        float2 Yf = make_float2(P0[s].x + P1[s].x,  P0[s].y + P1[s].y);
        float2 Ym = make_float2(P0[ms].x + P1[ms].x, P0[ms].y + P1[ms].y);
        float2 A = make_float2(0.5f * (Yf.x + Ym.x), 0.5f * (Yf.y - Ym.y));
        float2 D = make_float2(0.5f * (Yf.x - Ym.x), 0.5f * (Yf.y + Ym.y));
        float2 tw = d_tw4[s];
        float2 B = make_float2(D.x * tw.x + D.y * tw.y,   // D * conj(tw)
                               D.y * tw.x - D.x * tw.y);
        float2 Z = make_float2(A.x - B.y, A.y + B.x);
        buf[addr2048(s)] = make_float2(Z.x, -Z.y);         // conj for inv-via-fwd
    }
    fft2048_core(buf);
    const float inv = 1.0f / 2048.0f;
    float2* out2 = (float2*)out;
    for (int k = threadIdx.x; k < 1024; k += 256) {
        float2 F = buf[k];
        out2[r * 1024 + k] = make_float2(F.x * inv, -F.y * inv);
    }
}

// ============================================================================
extern "C" void kernel_launch(void* const* d_in, const int* in_sizes, int n_in,
                              void* d_out, int out_size) {
    (void)in_sizes; (void)n_in; (void)out_size;
    const float* x  = (const float*)d_in[0];
    const float* W1 = (const float*)d_in[1];
    const float* W2 = (const float*)d_in[2];
    const float* W3 = (const float*)d_in[3];
    float* out = (float*)d_out;

    cudaFuncSetAttribute(k45_kernel,
                         cudaFuncAttributeMaxDynamicSharedMemorySize, K45_SMEM);

    setup_h2_kernel<<<2048, 256>>>(W1, W2, W3);
    fft_gx_kernel<<<128, 512>>>(x);
    k45_kernel<<<dim3(129, 2), 256, K45_SMEM>>>();
    fft_inv_kernel<<<128, 256>>>(out);
}